// round 1
// baseline (speedup 1.0000x reference)
#include <cuda_runtime.h>
#include <cstdint>

// ---------------------------------------------------------------------------
// SphericalExpansion: per-edge outer product (radial basis x real sph. harm.)
// scattered into segment sums keyed by (idx_i, species[idx_j]).
//
// Layout: one WARP per edge. Lane L owns output floats [4L, 4L+4) of the
// edge's 128-float block:  n = L>>2 (radial index), lm = (L&3)*4 .. +3.
// Lane L also computes rb[k=L] = exp(-2 (r - center_L)^2) * fc(r)
// (k = l*8 + n), so one MUFU per lane covers all 32 radial values; the
// needed rb[l][n] values are fetched with 4 warp shuffles.
// Scatter uses red.global.add.v4.f32 (sm_90+): 32 lanes x 16B = one
// contiguous 512B block per edge.
// ---------------------------------------------------------------------------

#ifndef __CUDACC__
#define __launch_bounds__(...)
#endif

__global__ void __launch_bounds__(256) zero_out_kernel(float4* out, int n4) {
    int i = blockIdx.x * blockDim.x + threadIdx.x;
    int stride = gridDim.x * blockDim.x;
    float4 z = make_float4(0.f, 0.f, 0.f, 0.f);
    for (; i < n4; i += stride) out[i] = z;
}

__global__ void __launch_bounds__(256) sph_expand_kernel(
    const float* __restrict__ dist,
    const float* __restrict__ dirs,      // [J,3]
    const float* __restrict__ centers,   // [32] = (LMAX+1)*NMAX
    const int*   __restrict__ zspec,     // [N_ATOMS]
    const int*   __restrict__ idx_i,     // [J]
    const int*   __restrict__ idx_j,     // [J]
    float*       __restrict__ out,       // [N_ATOMS*4*8*16]
    int J)
{
    const int lane  = threadIdx.x & 31;
    const int warp  = (blockIdx.x * blockDim.x + threadIdx.x) >> 5;
    const int nwarp = (gridDim.x * blockDim.x) >> 5;

    const float c_k = centers[lane];   // k = l*8 + n for this lane
    const int   n   = lane >> 2;       // radial index owned by this lane
    const int   g   = lane & 3;        // which group of 4 lm values

    for (int e = warp; e < J; e += nwarp) {
        const float r  = dist[e];
        const float x  = dirs[3 * e + 0];
        const float y  = dirs[3 * e + 1];
        const float zz = dirs[3 * e + 2];
        const int   ii = idx_i[e];
        const int   zj = zspec[idx_j[e]];

        // shifted cosine cutoff: rc=5, w=0.5
        float fc;
        if (r < 4.5f)      fc = 1.0f;
        else if (r < 5.0f) fc = 0.5f * (1.0f + cospif((r - 4.5f) * 2.0f));
        else               fc = 0.0f;

        // radial basis for this lane's center (sigma=0.5 -> -0.5/sigma^2 = -2)
        const float t  = r - c_k;
        const float rb = __expf(-2.0f * t * t) * fc;

        // gather rb[l][n] for l = 0..3 at this lane's n
        const unsigned m = 0xffffffffu;
        const float rb0 = __shfl_sync(m, rb, n);
        const float rb1 = __shfl_sync(m, rb, 8  + n);
        const float rb2 = __shfl_sync(m, rb, 16 + n);
        const float rb3 = __shfl_sync(m, rb, 24 + n);

        const float x2 = x * x, y2 = y * y, z2 = zz * zz;

        float v0, v1, v2, v3;
        if (g == 0) {               // lm 0..3 : l = 0,1,1,1
            v0 = 0.28209479177387814f * rb0;
            v1 = 0.4886025119029199f * y  * rb1;
            v2 = 0.4886025119029199f * zz * rb1;
            v3 = 0.4886025119029199f * x  * rb1;
        } else if (g == 1) {        // lm 4..7 : l = 2
            v0 = 1.0925484305920792f  * x * y  * rb2;
            v1 = 1.0925484305920792f  * y * zz * rb2;
            v2 = 0.31539156525252005f * (2.0f * z2 - x2 - y2) * rb2;
            v3 = 1.0925484305920792f  * x * zz * rb2;
        } else if (g == 2) {        // lm 8..11 : l = 2,3,3,3
            v0 = 0.5462742152960396f * (x2 - y2) * rb2;
            v1 = 0.5900435899266435f * y * (3.0f * x2 - y2) * rb3;
            v2 = 2.890611442640554f  * x * y * zz * rb3;
            v3 = 0.4570457994644658f * y * (4.0f * z2 - x2 - y2) * rb3;
        } else {                    // lm 12..15 : l = 3
            v0 = 0.3731763325901154f * zz * (2.0f * z2 - 3.0f * x2 - 3.0f * y2) * rb3;
            v1 = 0.4570457994644658f * x  * (4.0f * z2 - x2 - y2) * rb3;
            v2 = 1.445305721320277f  * zz * (x2 - y2) * rb3;
            v3 = 0.5900435899266435f * x  * (x2 - 3.0f * y2) * rb3;
        }

        // segment id = idx_i*4 + z[idx_j]; 128 floats per segment
        float* p = out + (((size_t)ii * 4 + (size_t)zj) << 7) + ((size_t)lane << 2);
        asm volatile("red.global.add.v4.f32 [%0], {%1,%2,%3,%4};"
                     :: "l"(p), "f"(v0), "f"(v1), "f"(v2), "f"(v3)
                     : "memory");
    }
}

extern "C" void kernel_launch(void* const* d_in, const int* in_sizes, int n_in,
                              void* d_out, int out_size) {
    const float* dist    = (const float*)d_in[0];
    const float* dirs    = (const float*)d_in[1];
    const float* centers = (const float*)d_in[2];
    const int*   zspec   = (const int*)d_in[3];
    const int*   idx_i   = (const int*)d_in[4];
    const int*   idx_j   = (const int*)d_in[5];
    float*       out     = (float*)d_out;
    const int J = in_sizes[0];

    // zero the (0xAA-poisoned) output each call
    const int n4 = out_size / 4;                    // out_size = 10,240,000 floats
    zero_out_kernel<<<1184, 256>>>((float4*)d_out, n4);

    // one warp per edge, grid-stride
    const int blocks = 148 * 16;                    // 18944 warps
    sph_expand_kernel<<<blocks, 256>>>(dist, dirs, centers, zspec,
                                       idx_i, idx_j, out, J);
}

// round 2
// speedup vs baseline: 1.2317x; 1.2317x over previous
#include <cuda_runtime.h>
#include <cstdint>

// ---------------------------------------------------------------------------
// SphericalExpansion, round 2: branchless table-driven Ylm.
//
// One WARP per edge. Lane L:
//   - computes rb[k=L] = exp(-2 (r-center_L)^2) * fc(r)   (k = l*8+n)
//   - computes Y[lm=L&15] = f1(x,y,z) * f2(x2,y2,z2,xy,yz,zx)
//     with per-lane constant coefficient vectors (no divergence)
//   - owns output floats [4L,4L+4): n = L>>2, lm = 4*(L&3)..+3
//   - fetches its 4 Y and 4 rb operands via shfl.idx (src lanes precomputed)
//   - one red.global.add.v4.f32 -> 512B contiguous per warp
// ---------------------------------------------------------------------------

// f1 coefficients per lm: f1 = a0 + ax*x + ay*y + az*z   (one-hot)
__constant__ float cA[16][4] = {
    {1,0,0,0}, {0,0,1,0}, {0,0,0,1}, {0,1,0,0},   // lm 0..3  : 1, y, z, x
    {1,0,0,0}, {1,0,0,0}, {1,0,0,0}, {1,0,0,0},   // lm 4..7  : 1
    {1,0,0,0}, {0,0,1,0}, {0,1,0,0}, {0,0,1,0},   // lm 8..11 : 1, y, x, y
    {0,0,0,1}, {0,1,0,0}, {0,0,0,1}, {0,1,0,0},   // lm 12..15: z, x, z, x
};

// f2 coefficients per lm: f2 = c0 + cx*x2 + cy*y2 + cz*z2 + cxy*xy + cyz*yz + czx*zx
__constant__ float cF[16][7] = {
    {0.28209479177387814f, 0,0,0, 0,0,0},
    {0.4886025119029199f,  0,0,0, 0,0,0},
    {0.4886025119029199f,  0,0,0, 0,0,0},
    {0.4886025119029199f,  0,0,0, 0,0,0},
    {0, 0,0,0, 1.0925484305920792f,0,0},                                   // xy
    {0, 0,0,0, 0,1.0925484305920792f,0},                                   // yz
    {0,-0.31539156525252005f,-0.31539156525252005f,0.6307831305050401f, 0,0,0},
    {0, 0,0,0, 0,0,1.0925484305920792f},                                   // xz
    {0, 0.5462742152960396f,-0.5462742152960396f,0, 0,0,0},
    {0, 1.7701307697799304f,-0.5900435899266435f,0, 0,0,0},                // y(3x2-y2)
    {0, 0,0,0, 0,2.890611442640554f,0},                                    // x*(yz)
    {0,-0.4570457994644658f,-0.4570457994644658f,1.8281831978578632f, 0,0,0},
    {0,-1.1195289977703462f,-1.1195289977703462f,0.7463526651802308f, 0,0,0},
    {0,-0.4570457994644658f,-0.4570457994644658f,1.8281831978578632f, 0,0,0},
    {0, 1.445305721320277f,-1.445305721320277f,0, 0,0,0},
    {0, 0.5900435899266435f,-1.7701307697799304f,0, 0,0,0},
};

__constant__ int cLM2L[16] = {0,1,1,1, 2,2,2,2, 2,3,3,3, 3,3,3,3};

__global__ void __launch_bounds__(256) zero_out_kernel(float4* out, int n4) {
    int i = blockIdx.x * blockDim.x + threadIdx.x;
    int stride = gridDim.x * blockDim.x;
    float4 z = make_float4(0.f, 0.f, 0.f, 0.f);
    for (; i < n4; i += stride) out[i] = z;
}

__global__ void __launch_bounds__(256) sph_expand_kernel(
    const float* __restrict__ dist,
    const float* __restrict__ dirs,      // [J,3]
    const float* __restrict__ centers,   // [32]
    const int*   __restrict__ zspec,     // [N_ATOMS]
    const int*   __restrict__ idx_i,     // [J]
    const int*   __restrict__ idx_j,     // [J]
    float*       __restrict__ out,       // [N_ATOMS*4*8*16]
    int J)
{
    const int lane  = threadIdx.x & 31;
    const int warp  = (blockIdx.x * blockDim.x + threadIdx.x) >> 5;
    const int nwarp = (gridDim.x * blockDim.x) >> 5;

    const int lm = lane & 15;           // which Y this lane produces
    const int n  = lane >> 2;           // radial index this lane owns
    const int g  = lane & 3;            // lm group (4 consecutive) this lane owns

    // per-lane constants (hoisted out of the loop)
    const float cen = centers[lane];
    const float a0 = cA[lm][0], ax = cA[lm][1], ay = cA[lm][2], az = cA[lm][3];
    const float f0 = cF[lm][0], fx = cF[lm][1], fy = cF[lm][2], fz = cF[lm][3];
    const float fxy = cF[lm][4], fyz = cF[lm][5], fzx = cF[lm][6];

    // shuffle source lanes for the 4 owned outputs
    const int sY0 = 4*g + 0, sY1 = 4*g + 1, sY2 = 4*g + 2, sY3 = 4*g + 3;
    const int sR0 = 8*cLM2L[sY0] + n;
    const int sR1 = 8*cLM2L[sY1] + n;
    const int sR2 = 8*cLM2L[sY2] + n;
    const int sR3 = 8*cLM2L[sY3] + n;

    float* const outLane = out + ((size_t)lane << 2);
    const unsigned m = 0xffffffffu;

    for (int e = warp; e < J; e += nwarp) {
        const float r  = __ldg(dist + e);
        const float x  = __ldg(dirs + 3 * e + 0);
        const float y  = __ldg(dirs + 3 * e + 1);
        const float zz = __ldg(dirs + 3 * e + 2);
        const int   ii = __ldg(idx_i + e);
        const int   zj = __ldg(zspec + __ldg(idx_j + e));

        // shifted cosine cutoff (warp-uniform branch; ~90% of warps take fast path)
        float fc = 1.0f;
        if (r >= 4.5f)
            fc = (r < 5.0f) ? 0.5f * (1.0f + cospif((r - 4.5f) * 2.0f)) : 0.0f;

        // radial basis for this lane's center (sigma=0.5 -> coeff -2)
        const float t  = r - cen;
        const float rb = __expf(-2.0f * t * t) * fc;

        // Y[lm] = f1 * f2 (branchless)
        const float x2 = x*x, y2 = y*y, z2 = zz*zz;
        const float xy = x*y, yz = y*zz, zx = zz*x;
        const float f1 = a0 + ax*x + ay*y + az*zz;
        const float f2 = f0 + fx*x2 + fy*y2 + fz*z2 + fxy*xy + fyz*yz + fzx*zx;
        const float Y  = f1 * f2;

        // gather the 4 (Y, rb) pairs this lane needs
        const float Y0 = __shfl_sync(m, Y, sY0);
        const float Y1 = __shfl_sync(m, Y, sY1);
        const float Y2 = __shfl_sync(m, Y, sY2);
        const float Y3 = __shfl_sync(m, Y, sY3);
        const float R0 = __shfl_sync(m, rb, sR0);
        const float R1 = __shfl_sync(m, rb, sR1);
        const float R2 = __shfl_sync(m, rb, sR2);
        const float R3 = __shfl_sync(m, rb, sR3);

        const float v0 = Y0 * R0;
        const float v1 = Y1 * R1;
        const float v2 = Y2 * R2;
        const float v3 = Y3 * R3;

        // segment id = idx_i*4 + z[idx_j]; 128 floats per segment
        float* p = outLane + (((size_t)((ii << 2) + zj)) << 7);
        asm volatile("red.global.add.v4.f32 [%0], {%1,%2,%3,%4};"
                     :: "l"(p), "f"(v0), "f"(v1), "f"(v2), "f"(v3)
                     : "memory");
    }
}

extern "C" void kernel_launch(void* const* d_in, const int* in_sizes, int n_in,
                              void* d_out, int out_size) {
    const float* dist    = (const float*)d_in[0];
    const float* dirs    = (const float*)d_in[1];
    const float* centers = (const float*)d_in[2];
    const int*   zspec   = (const int*)d_in[3];
    const int*   idx_i   = (const int*)d_in[4];
    const int*   idx_j   = (const int*)d_in[5];
    float*       out     = (float*)d_out;
    const int J = in_sizes[0];

    const int n4 = out_size / 4;
    zero_out_kernel<<<1184, 256>>>((float4*)d_out, n4);

    const int blocks = 148 * 16;   // 18944 warps, grid-stride over 800k edges
    sph_expand_kernel<<<blocks, 256>>>(dist, dirs, centers, zspec,
                                       idx_i, idx_j, out, J);
}

// round 3
// speedup vs baseline: 1.2718x; 1.0326x over previous
#include <cuda_runtime.h>
#include <cstdint>

// ---------------------------------------------------------------------------
// SphericalExpansion, round 3: 4-edge unroll (MLP on the zspec gather chain),
// 6 shuffles/edge (4 Y + 2 rb) with FSEL picks, branchless cutoff.
//
// One WARP per 4 edges per iteration. Lane L:
//   - computes rb[k=L] = exp(-2 (r-center_L)^2) * fc(r)   (k = l*8+n)
//   - computes Y[lm=L&15] = f1 * f2 (branchless per-lane coefficient tables)
//   - owns output floats [4L,4L+4): n = L>>2, lm group g = L&3
//   - gathers 4 Y + 2 rb via shfl.idx; picks rbA/rbB per position with FSEL
//   - one red.global.add.v4.f32 per edge -> contiguous 512B per warp
// ---------------------------------------------------------------------------

__constant__ float cA[16][4] = {   // f1 = a0 + ax*x + ay*y + az*z (one-hot)
    {1,0,0,0}, {0,0,1,0}, {0,0,0,1}, {0,1,0,0},
    {1,0,0,0}, {1,0,0,0}, {1,0,0,0}, {1,0,0,0},
    {1,0,0,0}, {0,0,1,0}, {0,1,0,0}, {0,0,1,0},
    {0,0,0,1}, {0,1,0,0}, {0,0,0,1}, {0,1,0,0},
};

__constant__ float cF[16][7] = {   // f2 = c0+cx*x2+cy*y2+cz*z2+cxy*xy+cyz*yz+czx*zx
    {0.28209479177387814f, 0,0,0, 0,0,0},
    {0.4886025119029199f,  0,0,0, 0,0,0},
    {0.4886025119029199f,  0,0,0, 0,0,0},
    {0.4886025119029199f,  0,0,0, 0,0,0},
    {0, 0,0,0, 1.0925484305920792f,0,0},
    {0, 0,0,0, 0,1.0925484305920792f,0},
    {0,-0.31539156525252005f,-0.31539156525252005f,0.6307831305050401f, 0,0,0},
    {0, 0,0,0, 0,0,1.0925484305920792f},
    {0, 0.5462742152960396f,-0.5462742152960396f,0, 0,0,0},
    {0, 1.7701307697799304f,-0.5900435899266435f,0, 0,0,0},
    {0, 0,0,0, 0,2.890611442640554f,0},
    {0,-0.4570457994644658f,-0.4570457994644658f,1.8281831978578632f, 0,0,0},
    {0,-1.1195289977703462f,-1.1195289977703462f,0.7463526651802308f, 0,0,0},
    {0,-0.4570457994644658f,-0.4570457994644658f,1.8281831978578632f, 0,0,0},
    {0, 1.445305721320277f,-1.445305721320277f,0, 0,0,0},
    {0, 0.5900435899266435f,-1.7701307697799304f,0, 0,0,0},
};

__constant__ int cLM2L[16] = {0,1,1,1, 2,2,2,2, 2,3,3,3, 3,3,3,3};

__global__ void __launch_bounds__(256) zero_out_kernel(float4* out, int n4) {
    int i = blockIdx.x * blockDim.x + threadIdx.x;
    int stride = gridDim.x * blockDim.x;
    float4 zv = make_float4(0.f, 0.f, 0.f, 0.f);
    for (; i < n4; i += stride) out[i] = zv;
}

__global__ void __launch_bounds__(256) sph_expand_kernel(
    const float* __restrict__ dist,
    const float* __restrict__ dirs,      // [J,3]
    const float* __restrict__ centers,   // [32]
    const int*   __restrict__ zspec,     // [N_ATOMS]
    const int*   __restrict__ idx_i,     // [J]
    const int*   __restrict__ idx_j,     // [J]
    float*       __restrict__ out,       // [N_ATOMS*4*8*16]
    int J)
{
    const int lane  = threadIdx.x & 31;
    const int warp  = (blockIdx.x * blockDim.x + threadIdx.x) >> 5;
    const int nwarp = (gridDim.x * blockDim.x) >> 5;

    const int lm = lane & 15;
    const int n  = lane >> 2;
    const int g  = lane & 3;

    // per-lane constants (hoisted)
    const float cen = centers[lane];
    const float a0 = cA[lm][0], ax = cA[lm][1], ay = cA[lm][2], az = cA[lm][3];
    const float f0 = cF[lm][0], fx = cF[lm][1], fy = cF[lm][2], fz = cF[lm][3];
    const float fxy = cF[lm][4], fyz = cF[lm][5], fzx = cF[lm][6];

    // shuffle sources: 4 Y lanes, 2 rb lanes; per-position rbA/rbB picks
    const int sY0 = 4*g + 0, sY1 = 4*g + 1, sY2 = 4*g + 2, sY3 = 4*g + 3;
    const int lA = cLM2L[sY0], lB = cLM2L[sY3];
    const int sRA = 8*lA + n, sRB = 8*lB + n;
    const bool p1 = (cLM2L[sY1] != lA);
    const bool p2 = (cLM2L[sY2] != lA);
    const bool p3 = (cLM2L[sY3] != lA);

    float* const outLane = out + ((size_t)lane << 2);
    const unsigned m = 0xffffffffu;

    const int Jmain = J & ~3;

    for (int e0 = warp * 4; e0 < Jmain; e0 += nwarp * 4) {
        // ---- phase 1: all loads for 4 edges (MLP=4 on the zspec chain) ----
        float r[4], x[4], y[4], zc[4];
        int   seg[4];
        int   jj[4];
        #pragma unroll
        for (int k = 0; k < 4; k++) jj[k] = __ldg(idx_j + e0 + k);
        #pragma unroll
        for (int k = 0; k < 4; k++) {
            const int e = e0 + k;
            r[k]  = __ldg(dist + e);
            x[k]  = __ldg(dirs + 3 * e + 0);
            y[k]  = __ldg(dirs + 3 * e + 1);
            zc[k] = __ldg(dirs + 3 * e + 2);
            const int ii = __ldg(idx_i + e);
            const int zj = __ldg(zspec + jj[k]);
            seg[k] = (ii << 2) + zj;
        }

        // ---- phase 2: compute + scatter each edge ----
        #pragma unroll
        for (int k = 0; k < 4; k++) {
            const float rr = r[k], xx = x[k], yy = y[k], zz = zc[k];

            // branchless shifted-cosine cutoff (rc=5, w=0.5)
            const float u  = __saturatef((rr - 4.5f) * 2.0f);
            const float fc = 0.5f + 0.5f * cospif(u);

            // radial basis for this lane's center (sigma=0.5 -> -2)
            const float t  = rr - cen;
            const float rb = __expf(-2.0f * t * t) * fc;

            // Y[lm] = f1 * f2 (branchless)
            const float x2 = xx*xx, y2 = yy*yy, z2 = zz*zz;
            const float xy = xx*yy, yz = yy*zz, zx = zz*xx;
            const float f1 = a0 + ax*xx + ay*yy + az*zz;
            const float f2 = f0 + fx*x2 + fy*y2 + fz*z2 + fxy*xy + fyz*yz + fzx*zx;
            const float Y  = f1 * f2;

            // gather 4 Y + 2 rb
            const float Y0  = __shfl_sync(m, Y,  sY0);
            const float Y1  = __shfl_sync(m, Y,  sY1);
            const float Y2  = __shfl_sync(m, Y,  sY2);
            const float Y3  = __shfl_sync(m, Y,  sY3);
            const float rbA = __shfl_sync(m, rb, sRA);
            const float rbB = __shfl_sync(m, rb, sRB);

            const float v0 = Y0 * rbA;
            const float v1 = Y1 * (p1 ? rbB : rbA);
            const float v2 = Y2 * (p2 ? rbB : rbA);
            const float v3 = Y3 * (p3 ? rbB : rbA);

            float* p = outLane + ((size_t)seg[k] << 7);
            asm volatile("red.global.add.v4.f32 [%0], {%1,%2,%3,%4};"
                         :: "l"(p), "f"(v0), "f"(v1), "f"(v2), "f"(v3)
                         : "memory");
        }
    }

    // tail (J not multiple of 4)
    for (int e = Jmain + warp; e < J; e += nwarp) {
        const float rr = __ldg(dist + e);
        const float xx = __ldg(dirs + 3 * e + 0);
        const float yy = __ldg(dirs + 3 * e + 1);
        const float zz = __ldg(dirs + 3 * e + 2);
        const int   ii = __ldg(idx_i + e);
        const int   zj = __ldg(zspec + __ldg(idx_j + e));

        const float u  = __saturatef((rr - 4.5f) * 2.0f);
        const float fc = 0.5f + 0.5f * cospif(u);
        const float t  = rr - cen;
        const float rb = __expf(-2.0f * t * t) * fc;

        const float x2 = xx*xx, y2 = yy*yy, z2 = zz*zz;
        const float xy = xx*yy, yz = yy*zz, zx = zz*xx;
        const float f1 = a0 + ax*xx + ay*yy + az*zz;
        const float f2 = f0 + fx*x2 + fy*y2 + fz*z2 + fxy*xy + fyz*yz + fzx*zx;
        const float Y  = f1 * f2;

        const float Y0  = __shfl_sync(m, Y,  sY0);
        const float Y1  = __shfl_sync(m, Y,  sY1);
        const float Y2  = __shfl_sync(m, Y,  sY2);
        const float Y3  = __shfl_sync(m, Y,  sY3);
        const float rbA = __shfl_sync(m, rb, sRA);
        const float rbB = __shfl_sync(m, rb, sRB);

        const float v0 = Y0 * rbA;
        const float v1 = Y1 * (p1 ? rbB : rbA);
        const float v2 = Y2 * (p2 ? rbB : rbA);
        const float v3 = Y3 * (p3 ? rbB : rbA);

        float* p = outLane + ((size_t)((ii << 2) + zj) << 7);
        asm volatile("red.global.add.v4.f32 [%0], {%1,%2,%3,%4};"
                     :: "l"(p), "f"(v0), "f"(v1), "f"(v2), "f"(v3)
                     : "memory");
    }
}

extern "C" void kernel_launch(void* const* d_in, const int* in_sizes, int n_in,
                              void* d_out, int out_size) {
    const float* dist    = (const float*)d_in[0];
    const float* dirs    = (const float*)d_in[1];
    const float* centers = (const float*)d_in[2];
    const int*   zspec   = (const int*)d_in[3];
    const int*   idx_i   = (const int*)d_in[4];
    const int*   idx_j   = (const int*)d_in[5];
    float*       out     = (float*)d_out;
    const int J = in_sizes[0];

    const int n4 = out_size / 4;
    zero_out_kernel<<<1184, 256>>>((float4*)d_out, n4);

    const int blocks = 148 * 16;   // 18944 warps, 4-edge packs, grid-stride
    sph_expand_kernel<<<blocks, 256>>>(dist, dirs, centers, zspec,
                                       idx_i, idx_j, out, J);
}

// round 4
// speedup vs baseline: 1.3296x; 1.0455x over previous
#include <cuda_runtime.h>
#include <cstdint>

// ---------------------------------------------------------------------------
// SphericalExpansion, round 4: strided output ownership -> zero Y-shuffles.
//
// One WARP per 4-edge pack. Lane L:
//   - computes rb[k=L] = exp(-2 (r-center_L)^2)*fc(r)  (k = l*8+n)
//   - computes Y[lm=L&15] = f1*f2 (branchless coefficient tables)
//   - owns the segment floats {L, L+32, L+64, L+96}: all have lm = L&15
//     (its OWN Y) and n = (L>>4)+2k -> 4 rb gathered via shfl.idx
//   - 4x red.global.add.f32 at [p], [p+32], [p+64], [p+96]: each covers one
//     contiguous 128B wavefront across the warp (same traffic as red.v4)
// Batch loads per pack: float4/int4 (10 LDGs for 4 edges).
// ---------------------------------------------------------------------------

__constant__ float cA[16][4] = {   // f1 = a0 + ax*x + ay*y + az*z (one-hot)
    {1,0,0,0}, {0,0,1,0}, {0,0,0,1}, {0,1,0,0},
    {1,0,0,0}, {1,0,0,0}, {1,0,0,0}, {1,0,0,0},
    {1,0,0,0}, {0,0,1,0}, {0,1,0,0}, {0,0,1,0},
    {0,0,0,1}, {0,1,0,0}, {0,0,0,1}, {0,1,0,0},
};

__constant__ float cF[16][7] = {   // f2 = c0+cx*x2+cy*y2+cz*z2+cxy*xy+cyz*yz+czx*zx
    {0.28209479177387814f, 0,0,0, 0,0,0},
    {0.4886025119029199f,  0,0,0, 0,0,0},
    {0.4886025119029199f,  0,0,0, 0,0,0},
    {0.4886025119029199f,  0,0,0, 0,0,0},
    {0, 0,0,0, 1.0925484305920792f,0,0},
    {0, 0,0,0, 0,1.0925484305920792f,0},
    {0,-0.31539156525252005f,-0.31539156525252005f,0.6307831305050401f, 0,0,0},
    {0, 0,0,0, 0,0,1.0925484305920792f},
    {0, 0.5462742152960396f,-0.5462742152960396f,0, 0,0,0},
    {0, 1.7701307697799304f,-0.5900435899266435f,0, 0,0,0},
    {0, 0,0,0, 0,2.890611442640554f,0},
    {0,-0.4570457994644658f,-0.4570457994644658f,1.8281831978578632f, 0,0,0},
    {0,-1.1195289977703462f,-1.1195289977703462f,0.7463526651802308f, 0,0,0},
    {0,-0.4570457994644658f,-0.4570457994644658f,1.8281831978578632f, 0,0,0},
    {0, 1.445305721320277f,-1.445305721320277f,0, 0,0,0},
    {0, 0.5900435899266435f,-1.7701307697799304f,0, 0,0,0},
};

__constant__ int cLM2L[16] = {0,1,1,1, 2,2,2,2, 2,3,3,3, 3,3,3,3};

__global__ void __launch_bounds__(256) zero_out_kernel(float4* out, int n4) {
    int i = blockIdx.x * blockDim.x + threadIdx.x;
    int stride = gridDim.x * blockDim.x;
    float4 zv = make_float4(0.f, 0.f, 0.f, 0.f);
    for (; i < n4; i += stride) out[i] = zv;
}

__device__ __forceinline__ void red_f32(float* p, float v) {
    asm volatile("red.global.add.f32 [%0], %1;" :: "l"(p), "f"(v) : "memory");
}

__global__ void __launch_bounds__(256, 5) sph_expand_kernel(
    const float* __restrict__ dist,
    const float* __restrict__ dirs,      // [J,3]
    const float* __restrict__ centers,   // [32]
    const int*   __restrict__ zspec,     // [N_ATOMS]
    const int*   __restrict__ idx_i,     // [J]
    const int*   __restrict__ idx_j,     // [J]
    float*       __restrict__ out,       // [N_ATOMS*4*8*16]
    int J)
{
    const int lane  = threadIdx.x & 31;
    const int warp  = (blockIdx.x * blockDim.x + threadIdx.x) >> 5;
    const int nwarp = (gridDim.x * blockDim.x) >> 5;

    const int lm = lane & 15;
    const int h  = lane >> 4;            // low bit of owned n
    const int l  = cLM2L[lm];

    // per-lane constants
    const float cen = centers[lane];     // lane as (l=lane>>3, n=lane&7)
    const float a0 = cA[lm][0], ax = cA[lm][1], ay = cA[lm][2], az = cA[lm][3];
    const float f0 = cF[lm][0], fx = cF[lm][1], fy = cF[lm][2], fz = cF[lm][3];
    const float fxy = cF[lm][4], fyz = cF[lm][5], fzx = cF[lm][6];

    // rb shuffle sources: rb[l][n] lives in lane 8*l+n; owned n = h+2k
    const int sR0 = 8*l + h;
    const int sR1 = sR0 + 2;
    const int sR2 = sR0 + 4;
    const int sR3 = sR0 + 6;

    float* const outLane = out + lane;   // float offset L within segment block
    const unsigned m = 0xffffffffu;

    const int npacks = J >> 2;
    const float4* __restrict__ dist4 = (const float4*)dist;
    const float4* __restrict__ dirs4 = (const float4*)dirs;
    const int4*   __restrict__ ii4p  = (const int4*)idx_i;
    const int4*   __restrict__ jj4p  = (const int4*)idx_j;

    for (int pk = warp; pk < npacks; pk += nwarp) {
        // ---- batch loads: 4 edges, 10 LDGs ----
        const float4 r4 = __ldg(dist4 + pk);
        const float4 d0 = __ldg(dirs4 + 3*pk + 0);
        const float4 d1 = __ldg(dirs4 + 3*pk + 1);
        const float4 d2 = __ldg(dirs4 + 3*pk + 2);
        const int4   i4 = __ldg(ii4p + pk);
        const int4   j4 = __ldg(jj4p + pk);

        const int z0 = __ldg(zspec + j4.x);
        const int z1 = __ldg(zspec + j4.y);
        const int z2 = __ldg(zspec + j4.z);
        const int z3 = __ldg(zspec + j4.w);

        const float rr[4] = {r4.x, r4.y, r4.z, r4.w};
        const float xx[4] = {d0.x, d0.w, d1.z, d2.y};
        const float yy[4] = {d0.y, d1.x, d1.w, d2.z};
        const float zzv[4] = {d0.z, d1.y, d2.x, d2.w};
        const int  seg[4] = {(i4.x<<2)+z0, (i4.y<<2)+z1, (i4.z<<2)+z2, (i4.w<<2)+z3};

        #pragma unroll
        for (int k = 0; k < 4; k++) {
            const float r = rr[k], x = xx[k], y = yy[k], zz = zzv[k];

            // branchless shifted-cosine cutoff (rc=5, w=0.5)
            const float u  = __saturatef((r - 4.5f) * 2.0f);
            const float fc = 0.5f + 0.5f * cospif(u);

            // radial basis for this lane's center (sigma=0.5 -> -2)
            const float t  = r - cen;
            const float rb = __expf(-2.0f * t * t) * fc;

            // Y[lm] for this lane (fixed lm = lane&15)
            const float x2 = x*x, y2 = y*y, z2 = zz*zz;
            const float xy = x*y, yz = y*zz, zx = zz*x;
            const float f1 = a0 + ax*x + ay*y + az*zz;
            const float f2 = f0 + fx*x2 + fy*y2 + fz*z2 + fxy*xy + fyz*yz + fzx*zx;
            const float Y  = f1 * f2;

            // gather the 4 rb values (n = h, h+2, h+4, h+6)
            const float R0 = __shfl_sync(m, rb, sR0);
            const float R1 = __shfl_sync(m, rb, sR1);
            const float R2 = __shfl_sync(m, rb, sR2);
            const float R3 = __shfl_sync(m, rb, sR3);

            float* p = outLane + ((size_t)seg[k] << 7);
            red_f32(p,      Y * R0);
            red_f32(p + 32, Y * R1);
            red_f32(p + 64, Y * R2);
            red_f32(p + 96, Y * R3);
        }
    }

    // tail (J not a multiple of 4)
    for (int e = (npacks << 2) + warp; e < J; e += nwarp) {
        const float r  = __ldg(dist + e);
        const float x  = __ldg(dirs + 3*e + 0);
        const float y  = __ldg(dirs + 3*e + 1);
        const float zz = __ldg(dirs + 3*e + 2);
        const int   ii = __ldg(idx_i + e);
        const int   zj = __ldg(zspec + __ldg(idx_j + e));

        const float u  = __saturatef((r - 4.5f) * 2.0f);
        const float fc = 0.5f + 0.5f * cospif(u);
        const float t  = r - cen;
        const float rb = __expf(-2.0f * t * t) * fc;

        const float x2 = x*x, y2 = y*y, z2 = zz*zz;
        const float xy = x*y, yz = y*zz, zx = zz*x;
        const float f1 = a0 + ax*x + ay*y + az*zz;
        const float f2 = f0 + fx*x2 + fy*y2 + fz*z2 + fxy*xy + fyz*yz + fzx*zx;
        const float Y  = f1 * f2;

        const float R0 = __shfl_sync(m, rb, sR0);
        const float R1 = __shfl_sync(m, rb, sR1);
        const float R2 = __shfl_sync(m, rb, sR2);
        const float R3 = __shfl_sync(m, rb, sR3);

        float* p = outLane + ((size_t)((ii << 2) + zj) << 7);
        red_f32(p,      Y * R0);
        red_f32(p + 32, Y * R1);
        red_f32(p + 64, Y * R2);
        red_f32(p + 96, Y * R3);
    }
}

extern "C" void kernel_launch(void* const* d_in, const int* in_sizes, int n_in,
                              void* d_out, int out_size) {
    const float* dist    = (const float*)d_in[0];
    const float* dirs    = (const float*)d_in[1];
    const float* centers = (const float*)d_in[2];
    const int*   zspec   = (const int*)d_in[3];
    const int*   idx_i   = (const int*)d_in[4];
    const int*   idx_j   = (const int*)d_in[5];
    float*       out     = (float*)d_out;
    const int J = in_sizes[0];

    const int n4 = out_size / 4;
    zero_out_kernel<<<1184, 256>>>((float4*)d_out, n4);

    const int blocks = 148 * 5;   // persistent-ish grid: 5 blocks/SM target
    sph_expand_kernel<<<blocks, 256>>>(dist, dirs, centers, zspec,
                                       idx_i, idx_j, out, J);
}